// round 12
// baseline (speedup 1.0000x reference)
#include <cuda_runtime.h>

// SSIM loss, fused separable 11x11 Gaussian, B=16 C=3 H=512 W=512 fp32.
// v12 = v11 (cp.async staging) + shared-product streamed vertical conv.
//   grid = (9 chunks, 48 planes) = 432 blocks, 128 thr, 4 cols/thread,
//   3 CTAs/SM. Register ring of 10 packed raw rows (i-5..i+4); rows i+5,
//   i+6 arrive via cp.async.cg 2-slot smem staging issued 2 rows ahead.
//   Vertical conv streams the 12 source rows ONCE, computing (a^2+b^2) and
//   (ab) once per source row and accumulating into BOTH output rows
//   (124 packed ops/pack/pair vs 154 row-at-a-time; mu accumulation fuses
//   the weight multiply into the fma).
//   Horizontal: scalar FFMA-imm from quad-buffered padded smem,
//   ONE __syncthreads per 2 rows. Finalize folded into the last block.

#define HH 512
#define WW 512
#define NTHREADS 128
#define NPIX 12582912.0
#define GX 9
#define GY 48
#define NBLOCKS (GX * GY)

typedef unsigned long long u64;

__device__ constexpr float KW[11] = {
    0.00102839f, 0.00759876f, 0.03600077f, 0.10936069f, 0.21300554f,
    0.26601172f,
    0.21300554f, 0.10936069f, 0.03600077f, 0.00759876f, 0.00102839f};

__device__ double g_partial[NBLOCKS];
__device__ unsigned g_count = 0;

// ---- f32x2 packed helpers (sm_100+ PTX) ----
__device__ __forceinline__ u64 pk2(float lo, float hi) {
    u64 r; asm("mov.b64 %0, {%1, %2};" : "=l"(r) : "f"(lo), "f"(hi)); return r;
}
__device__ __forceinline__ void upk2(u64 v, float& lo, float& hi) {
    asm("mov.b64 {%0, %1}, %2;" : "=f"(lo), "=f"(hi) : "l"(v));
}
__device__ __forceinline__ u64 f2add(u64 a, u64 b) {
    u64 r; asm("add.rn.f32x2 %0, %1, %2;" : "=l"(r) : "l"(a), "l"(b)); return r;
}
__device__ __forceinline__ u64 f2mul(u64 a, u64 b) {
    u64 r; asm("mul.rn.f32x2 %0, %1, %2;" : "=l"(r) : "l"(a), "l"(b)); return r;
}
__device__ __forceinline__ u64 f2fma(u64 a, u64 b, u64 c) {
    u64 r; asm("fma.rn.f32x2 %0, %1, %2, %3;" : "=l"(r) : "l"(a), "l"(b), "l"(c));
    return r;
}

// ---- cp.async helpers ----
__device__ __forceinline__ void cp16(unsigned dst, const float* src) {
    asm volatile("cp.async.cg.shared.global [%0], [%1], 16;"
                 :: "r"(dst), "l"(src));
}
#define CP_COMMIT() asm volatile("cp.async.commit_group;" ::: "memory")
#define CP_WAIT1()  asm volatile("cp.async.wait_group 1;" ::: "memory")

__device__ __forceinline__ void load_row_pk(const float* __restrict__ p,
                                            int row, int c0, u64 o[2]) {
    if ((unsigned)row < (unsigned)HH) {
        ulonglong2 v = *reinterpret_cast<const ulonglong2*>(p + row * WW + c0);
        o[0] = v.x;
        o[1] = v.y;
    } else {
        o[0] = 0ull; o[1] = 0ull;
    }
}

__global__ __launch_bounds__(NTHREADS, 3)
void ssim_kernel(const float* __restrict__ sr, const float* __restrict__ hr,
                 float* __restrict__ out) {
    const int plane = blockIdx.y;
    const int bx = blockIdx.x;
    // chunks: 58,58,58,58,56,56,56,56,56 (all even; sum = 512)
    const int r0 = (bx < 4) ? 58 * bx : (232 + 56 * (bx - 4));
    const int npairs = (bx < 4) ? 29 : 28;
    const int tid = threadIdx.x;
    const int c0 = tid * 4;

    const float* __restrict__ pa0 = sr + (size_t)plane * HH * WW + c0;
    const float* __restrict__ pb0 = hr + (size_t)plane * HH * WW + c0;

    // Quad-buffered line buffer: [buf 0..3][field 0..3], data col c at word
    // c+8, halo zeros at words [0..7] and [520..527].
    __shared__ __align__(16) float vsbuf[4][4][528];
    // cp.async staging: 2 slots (by incoming-row parity) x 2 tensors.
    __shared__ __align__(16) float stageA[2][WW];
    __shared__ __align__(16) float stageB[2][WW];

    {
        for (int q = tid; q < 256; q += NTHREADS) {
            int b = q >> 6;
            int f = (q >> 4) & 3;
            int k = q & 15;
            int idx = (k < 8) ? k : (512 + k);
            vsbuf[b][f][idx] = 0.f;
        }
    }
    __syncthreads();

    // staging smem addresses for this thread's 16B
    unsigned sA[2], sB[2];
#pragma unroll
    for (int s = 0; s < 2; ++s) {
        sA[s] = (unsigned)__cvta_generic_to_shared(&stageA[s][c0]);
        sB[s] = (unsigned)__cvta_generic_to_shared(&stageB[s][c0]);
    }

    // Packed weight constants (symmetric kernel -> 6 uniques).
    u64 WKP[6];
#pragma unroll
    for (int k = 0; k < 6; ++k) WKP[k] = pk2(KW[k], KW[k]);

    // Register ring: positions 0..9 hold source rows (i-5) .. (i+4).
    u64 rga[10][2], rgb[10][2];
#pragma unroll
    for (int k = 0; k < 10; ++k) {
        load_row_pk(pa0 - c0, r0 - 5 + k, c0, rga[k]);
        load_row_pk(pb0 - c0, r0 - 5 + k, c0, rgb[k]);
    }

    // Prologue staging: rows r0+5, r0+6 (both < HH since r0 <= 456).
    {
        int g5 = r0 + 5, g6 = r0 + 6;
        cp16(sA[g5 & 1], pa0 + g5 * WW);
        cp16(sB[g5 & 1], pb0 + g5 * WW);
        CP_COMMIT();
        cp16(sA[g6 & 1], pa0 + g6 * WW);
        cp16(sB[g6 & 1], pb0 + g6 * WW);
        CP_COMMIT();
    }

    const u64 TWO  = pk2(2.f, 2.f);
    const u64 NEG1 = pk2(-1.f, -1.f);
    const u64 C1   = pk2(1e-4f, 1e-4f);
    const u64 C2   = pk2(9e-4f, 9e-4f);

    float acc = 0.f;

#pragma unroll 2
    for (int p = 0; p < npairs; ++p) {
        const int bufA = (p & 1) * 2;
        const int bufB = bufA + 1;
        const int i = r0 + 2 * p;

        // ---- consume staged rows i+5, i+6; refill slots with i+7, i+8 ----
        u64 st5a[2], st5b[2], st6a[2], st6b[2];
        {
            const int g5 = i + 5, g6 = i + 6;
            const int sl5 = g5 & 1, sl6 = g6 & 1;

            CP_WAIT1();  // row g5 complete
            ulonglong2 ta = *reinterpret_cast<const ulonglong2*>(&stageA[sl5][c0]);
            ulonglong2 tb = *reinterpret_cast<const ulonglong2*>(&stageB[sl5][c0]);
            if (g5 >= HH) { ta.x = 0; ta.y = 0; tb.x = 0; tb.y = 0; }
            st5a[0] = ta.x; st5a[1] = ta.y; st5b[0] = tb.x; st5b[1] = tb.y;
            {
                int rc = (g5 + 2 < HH) ? (g5 + 2) : (HH - 1);
                cp16(sA[sl5], pa0 + rc * WW);
                cp16(sB[sl5], pb0 + rc * WW);
                CP_COMMIT();
            }

            CP_WAIT1();  // row g6 complete
            ta = *reinterpret_cast<const ulonglong2*>(&stageA[sl6][c0]);
            tb = *reinterpret_cast<const ulonglong2*>(&stageB[sl6][c0]);
            if (g6 >= HH) { ta.x = 0; ta.y = 0; tb.x = 0; tb.y = 0; }
            st6a[0] = ta.x; st6a[1] = ta.y; st6b[0] = tb.x; st6b[1] = tb.y;
            {
                int rc = (g6 + 2 < HH) ? (g6 + 2) : (HH - 1);
                cp16(sA[sl6], pa0 + rc * WW);
                cp16(sB[sl6], pb0 + rc * WW);
                CP_COMMIT();
            }
        }

        // ---- vertical conv streamed over 12 source rows ----
        // A = output row i   (taps s=0..10, weight KW[s])
        // B = output row i+1 (taps s=1..11, weight KW[s-1])
        // fields: 0=mu1, 1=mu2, 2=q(a^2+b^2), 3=p(ab)
        u64 A[4][2], B[4][2];
#pragma unroll
        for (int s = 0; s < 12; ++s) {
#pragma unroll
            for (int q = 0; q < 2; ++q) {
                u64 a, b;
                if (s < 10)      { a = rga[s][q]; b = rgb[s][q]; }
                else if (s == 10){ a = st5a[q];   b = st5b[q]; }
                else             { a = st6a[q];   b = st6b[q]; }
                u64 qrow = f2fma(b, b, f2mul(a, a));
                u64 ab = f2mul(a, b);
                if (s <= 10) {
                    const int wi = (s <= 5) ? s : (10 - s);
                    if (s == 0) {
                        A[0][q] = f2mul(WKP[wi], a);
                        A[1][q] = f2mul(WKP[wi], b);
                        A[2][q] = f2mul(WKP[wi], qrow);
                        A[3][q] = f2mul(WKP[wi], ab);
                    } else {
                        A[0][q] = f2fma(WKP[wi], a, A[0][q]);
                        A[1][q] = f2fma(WKP[wi], b, A[1][q]);
                        A[2][q] = f2fma(WKP[wi], qrow, A[2][q]);
                        A[3][q] = f2fma(WKP[wi], ab, A[3][q]);
                    }
                }
                if (s >= 1) {
                    const int k1 = s - 1;
                    const int wi = (k1 <= 5) ? k1 : (10 - k1);
                    if (s == 1) {
                        B[0][q] = f2mul(WKP[wi], a);
                        B[1][q] = f2mul(WKP[wi], b);
                        B[2][q] = f2mul(WKP[wi], qrow);
                        B[3][q] = f2mul(WKP[wi], ab);
                    } else {
                        B[0][q] = f2fma(WKP[wi], a, B[0][q]);
                        B[1][q] = f2fma(WKP[wi], b, B[1][q]);
                        B[2][q] = f2fma(WKP[wi], qrow, B[2][q]);
                        B[3][q] = f2fma(WKP[wi], ab, B[3][q]);
                    }
                }
            }
        }

        // publish vertical sums (one STS.128 per field per row)
#pragma unroll
        for (int f = 0; f < 4; ++f) {
            *reinterpret_cast<ulonglong2*>(&vsbuf[bufA][f][8 + c0]) =
                make_ulonglong2(A[f][0], A[f][1]);
            *reinterpret_cast<ulonglong2*>(&vsbuf[bufB][f][8 + c0]) =
                make_ulonglong2(B[f][0], B[f][1]);
        }

        // advance ring by 2 rows; staged rows enter the ring
#pragma unroll
        for (int k = 0; k < 8; ++k) {
#pragma unroll
            for (int q = 0; q < 2; ++q) {
                rga[k][q] = rga[k + 2][q];
                rgb[k][q] = rgb[k + 2][q];
            }
        }
#pragma unroll
        for (int q = 0; q < 2; ++q) {
            rga[8][q] = st5a[q]; rgb[8][q] = st5b[q];
            rga[9][q] = st6a[q]; rgb[9][q] = st6b[q];
        }

        __syncthreads();  // the only barrier per 2 rows

        // ---- horizontal conv + map, rows A and B (scalar FFMA-imm) ----
#pragma unroll
        for (int r = 0; r < 2; ++r) {
            const int buf = bufA + r;
            float cv[4][4];
#pragma unroll
            for (int f = 0; f < 4; ++f) {
                float v[20];
#pragma unroll
                for (int q5 = 0; q5 < 5; ++q5) {
                    float4 t = *reinterpret_cast<const float4*>(
                        &vsbuf[buf][f][c0 + 4 * q5]);
                    v[4 * q5 + 0] = t.x; v[4 * q5 + 1] = t.y;
                    v[4 * q5 + 2] = t.z; v[4 * q5 + 3] = t.w;
                }
#pragma unroll
                for (int j = 0; j < 4; ++j) {
                    float s = KW[5] * v[8 + j];
#pragma unroll
                    for (int k = 0; k < 11; ++k) {
                        if (k == 5) continue;
                        s += KW[k] * v[3 + j + k];
                    }
                    cv[f][j] = s;
                }
            }
#pragma unroll
            for (int q = 0; q < 2; ++q) {
                u64 m1 = pk2(cv[0][2 * q], cv[0][2 * q + 1]);
                u64 m2 = pk2(cv[1][2 * q], cv[1][2 * q + 1]);
                u64 q2 = pk2(cv[2][2 * q], cv[2][2 * q + 1]);
                u64 rr = pk2(cv[3][2 * q], cv[3][2 * q + 1]);
                u64 m12 = f2mul(m1, m2);
                u64 sms = f2fma(m2, m2, f2mul(m1, m1));
                u64 num1 = f2fma(TWO, m12, C1);
                u64 sig12 = f2fma(m12, NEG1, rr);
                u64 num2 = f2fma(TWO, sig12, C2);
                u64 den1 = f2add(sms, C1);
                u64 den2 = f2add(f2fma(sms, NEG1, q2), C2);
                u64 num = f2mul(num1, num2);
                u64 den = f2mul(den1, den2);
                float n0, n1, d0, d1;
                upk2(num, n0, n1);
                upk2(den, d0, d1);
                acc += __fdividef(n0, d0);
                acc += __fdividef(n1, d1);
            }
        }
        // no trailing barrier: next pair writes the other buffer set; reuse
        // of this set is fenced by the next __syncthreads.
    }

    // block reduction -> per-block partial
#pragma unroll
    for (int o = 16; o > 0; o >>= 1)
        acc += __shfl_down_sync(0xFFFFFFFFu, acc, o);

    __shared__ float wsum[4];
    __shared__ int is_last;
    if ((tid & 31) == 0) wsum[tid >> 5] = acc;
    __syncthreads();
    if (tid == 0) {
        double s = (double)wsum[0] + (double)wsum[1] + (double)wsum[2] +
                   (double)wsum[3];
        g_partial[blockIdx.y * GX + blockIdx.x] = s;
        __threadfence();
        unsigned old = atomicInc(&g_count, NBLOCKS - 1);  // wraps to 0
        is_last = (old == NBLOCKS - 1);
    }
    __syncthreads();

    // last block finalizes (replay-deterministic: counter wraps to 0)
    if (is_last) {
        __threadfence();
        double s = 0.0;
        for (int i2 = tid; i2 < NBLOCKS; i2 += NTHREADS)
            s += __ldcg(&g_partial[i2]);
#pragma unroll
        for (int o = 16; o > 0; o >>= 1)
            s += __shfl_down_sync(0xFFFFFFFFu, s, o);
        __shared__ double dsm[4];
        if ((tid & 31) == 0) dsm[tid >> 5] = s;
        __syncthreads();
        if (tid == 0) {
            double tot = dsm[0] + dsm[1] + dsm[2] + dsm[3];
            out[0] = (float)(1.0 - tot / NPIX);
        }
    }
}

extern "C" void kernel_launch(void* const* d_in, const int* in_sizes, int n_in,
                              void* d_out, int out_size) {
    const float* sr = (const float*)d_in[0];
    const float* hr = (const float*)d_in[1];
    float* out = (float*)d_out;

    dim3 grid(GX, GY);
    ssim_kernel<<<grid, NTHREADS>>>(sr, hr, out);
}